// round 10
// baseline (speedup 1.0000x reference)
#include <cuda_runtime.h>
#include <cuda_fp16.h>
#include <cstdint>

#define BATCH 4
#define CH    256
#define NPIX  4096
#define FTOT  321
#define FPAD  384
#define OUTOFF ((size_t)BATCH*CH*NPIX)
#define LOG2E 1.4426950408889634f
#define ONESH 0x3C003C00u

// ---------------- device scratch ----------------
__device__ __align__(16) uint16_t g_Wb[FPAD*CH];                 // fp16 packed weights [f][c] (q rows pre-scaled log2e)
__device__ float g_bias[FPAD];
__device__ float g_xmean[BATCH*CH];
__device__ float g_cbias[BATCH*64];
__device__ __align__(16) uint16_t g_Xt[(size_t)BATCH*NPIX*CH];   // fp16 x^T [b][n][c]
__device__ float g_Y[(size_t)BATCH*FTOT*NPIX];                   // fp32 (rows 0..63 q/k + row 320 pm)
__device__ float g_vmask[BATCH*CH];
__device__ __align__(16) uint32_t g_Qb[(size_t)BATCH*NPIX*16];   // fp16x2 [b][n][16]
__device__ __align__(16) uint32_t g_Kb[(size_t)BATCH*NPIX*16];
__device__ __align__(16) uint16_t g_Vb[(size_t)BATCH*CH*NPIX];   // fp16 [b][c][n]

// ---------------- helpers ----------------
__device__ __forceinline__ uint32_t smem_u32(const void* p) {
    uint32_t a;
    asm("{ .reg .u64 t; cvta.to.shared.u64 t, %1; cvt.u32.u64 %0, t; }" : "=r"(a) : "l"(p));
    return a;
}
__device__ __forceinline__ void ldsm4(uint32_t* r, uint32_t addr) {
    asm volatile("ldmatrix.sync.aligned.m8n8.x4.shared.b16 {%0,%1,%2,%3}, [%4];"
        : "=r"(r[0]), "=r"(r[1]), "=r"(r[2]), "=r"(r[3]) : "r"(addr));
}
__device__ __forceinline__ void mma16816(float* c, const uint32_t* a, uint32_t b0, uint32_t b1) {
    asm volatile("mma.sync.aligned.m16n8k16.row.col.f32.f16.f16.f32 "
        "{%0,%1,%2,%3}, {%4,%5,%6,%7}, {%8,%9}, {%0,%1,%2,%3};"
        : "+f"(c[0]), "+f"(c[1]), "+f"(c[2]), "+f"(c[3])
        : "r"(a[0]), "r"(a[1]), "r"(a[2]), "r"(a[3]), "r"(b0), "r"(b1));
}
__device__ __forceinline__ uint32_t h2pk(float lo, float hi) {
    __half2 h = __floats2half2_rn(lo, hi);
    return *(uint32_t*)&h;
}
__device__ __forceinline__ uint32_t hexp2pk(float lo, float hi) {
    __half2 h = h2exp2(__floats2half2_rn(lo, hi));
    return *(uint32_t*)&h;
}
#define CPA16(dst, src) asm volatile("cp.async.cg.shared.global [%0], [%1], 16;" :: "r"(dst), "l"(src))
#define CPA_COMMIT()    asm volatile("cp.async.commit_group;")
#define CPA_WAIT1()     asm volatile("cp.async.wait_group 1;")
#define CPA_WAIT0()     asm volatile("cp.async.wait_group 0;")

// ---------------- pack weights -> fp16, bias, zero xmean ----------------
__global__ void pack_kernel(const float* __restrict__ wq, const float* __restrict__ bq,
                            const float* __restrict__ wk, const float* __restrict__ bk,
                            const float* __restrict__ wv, const float* __restrict__ bv,
                            const float* __restrict__ wm, const float* __restrict__ bm) {
    int i  = blockIdx.x*blockDim.x + threadIdx.x;
    int nt = gridDim.x*blockDim.x;
    for (int idx = i; idx < FPAD*CH; idx += nt) {
        int f = idx >> 8, c = idx & 255;
        float v = 0.f;
        if      (f < 32)  v = wq[f*CH + c] * LOG2E;
        else if (f < 64)  v = wk[(f-32)*CH + c];
        else if (f < 320) v = wv[(f-64)*CH + c];
        else if (f == 320) v = wm[c];
        g_Wb[idx] = __half_as_ushort(__float2half_rn(v));
    }
    if (i < FPAD) {
        float bia = 0.f;
        if (i >= 64 && i < 320) bia = bv[i-64];
        else if (i == 320)      bia = bm[0];
        g_bias[i] = bia;
    }
    if (i < BATCH*CH) g_xmean[i] = 0.f;
}

// ---------------- x -> fp16 transpose [b][n][c] + channel sums + copy x->out ----------------
__global__ void __launch_bounds__(256) xconv_kernel(const float* __restrict__ x, float* __restrict__ out) {
    __shared__ float sm[64][133];
    __shared__ float msum[64];
    int nt = blockIdx.x, ct = blockIdx.y, b = blockIdx.z;
    int n0 = nt*128, c0 = ct*64;
    int t = threadIdx.x;
    if (t < 64) msum[t] = 0.f;
    __syncthreads();
    #pragma unroll
    for (int r = 0; r < 8; r++) {
        int idx = t + r*256;
        int ci = idx >> 5, n4 = idx & 31;
        size_t off = ((size_t)(b*CH + c0 + ci))*NPIX + n0 + n4*4;
        float4 v = *(const float4*)&x[off];
        *(float4*)&out[off] = v;                       // fused x copy
        sm[ci][n4*4+0]=v.x; sm[ci][n4*4+1]=v.y; sm[ci][n4*4+2]=v.z; sm[ci][n4*4+3]=v.w;
        atomicAdd(&msum[ci], (v.x+v.y)+(v.z+v.w));
    }
    __syncthreads();
    if (t < 64) atomicAdd(&g_xmean[b*CH + c0 + t], msum[t]);
    #pragma unroll
    for (int r = 0; r < 4; r++) {
        int idx = t + r*256;
        int ni = idx >> 3, ch = idx & 7;
        uint32_t p[4];
        #pragma unroll
        for (int e = 0; e < 4; e++)
            p[e] = h2pk(sm[ch*8 + 2*e][ni], sm[ch*8 + 2*e + 1][ni]);
        uint4 o; o.x=p[0]; o.y=p[1]; o.z=p[2]; o.w=p[3];
        *(uint4*)(g_Xt + ((size_t)b*NPIX + n0 + ni)*CH + c0 + ch*8) = o;
    }
}

// ---------------- cbias[b][f] = -W[f].xmean[b] ----------------
__global__ void cbias_kernel() {
    int b = blockIdx.x, f = threadIdx.x;   // 64 threads
    float s = 0.f;
    for (int c = 0; c < CH; c++)
        s += __half2float(__ushort_as_half(g_Wb[f*CH + c])) * g_xmean[b*CH + c];
    g_cbias[b*64 + f] = -s * (1.f/NPIX);
}

// ---------------- fp16 tensor-core GEMM: Y = W @ x^T, K-chunk pipelined (unchanged) ----------------
#define GSTAGE 49152
#define GEMM_SMEM (2*GSTAGE)
__global__ void __launch_bounds__(256, 2) gemm2_kernel() {
    extern __shared__ __align__(128) char gsm[];
    uint32_t sb = smem_u32(gsm);
    int t = threadIdx.x, w = t >> 5, lane = t & 31;
    int nt = blockIdx.x, ft = blockIdx.y, b = blockIdx.z;
    int n0g = nt*64, fbase0 = ft*128;

    const uint16_t* Wsrc = g_Wb + (size_t)fbase0*CH;
    const uint16_t* Xsrc = g_Xt + ((size_t)b*NPIX + n0g)*CH;

    #pragma unroll
    for (int kc = 0; kc < 2; kc++) {
        uint32_t sA = sb + kc*GSTAGE, sB = sA + 32768;
        #pragma unroll
        for (int r = 0; r < 8; r++) {
            int idx = t + r*256;
            int f = idx >> 4, j = idx & 15;
            CPA16(sA + f*256 + ((j*16) ^ ((f & 7) << 4)), (const char*)(Wsrc + f*CH + kc*128 + j*8));
        }
        #pragma unroll
        for (int r = 0; r < 4; r++) {
            int idx = t + r*256;
            int n = idx >> 4, j = idx & 15;
            CPA16(sB + n*256 + ((j*16) ^ ((n & 7) << 4)), (const char*)(Xsrc + n*CH + kc*128 + j*8));
        }
        CPA_COMMIT();
    }

    int wm = w >> 1, wn = w & 1;
    uint32_t arow = (uint32_t)(lane & 15), acsel = (uint32_t)((lane >> 4)*16);
    uint32_t axor = (uint32_t)((lane & 7) << 4);
    int lq = lane >> 3, lr = lane & 7;
    uint32_t lrow = (uint32_t)((lq >> 1)*8 + lr), lcsel = (uint32_t)((lq & 1)*16);
    uint32_t bxor = (uint32_t)(lr << 4);

    float acc[2][4][4];
    #pragma unroll
    for (int mi = 0; mi < 2; mi++)
        #pragma unroll
        for (int nj = 0; nj < 4; nj++)
            #pragma unroll
            for (int e = 0; e < 4; e++) acc[mi][nj][e] = 0.f;

    #pragma unroll
    for (int kc = 0; kc < 2; kc++) {
        if (kc == 0) CPA_WAIT1(); else CPA_WAIT0();
        __syncthreads();
        uint32_t sA = sb + kc*GSTAGE, sB = sA + 32768;
        uint32_t aAdr0 = sA + (wm*32 + arow)*256;
        uint32_t aAdr1 = sA + (wm*32 + 16 + arow)*256;
        uint32_t bAdr0 = sB + (wn*32 + lrow)*256;
        uint32_t bAdr1 = sB + (wn*32 + 16 + lrow)*256;
        #pragma unroll
        for (int k = 0; k < 8; k++) {
            uint32_t off_a = (((uint32_t)k*32 + acsel) ^ axor);
            uint32_t off_b = (((uint32_t)k*32 + lcsel) ^ bxor);
            uint32_t a0[4], a1[4], b0[4], b1[4];
            ldsm4(a0, aAdr0 + off_a);
            ldsm4(a1, aAdr1 + off_a);
            ldsm4(b0, bAdr0 + off_b);
            ldsm4(b1, bAdr1 + off_b);
            mma16816(acc[0][0], a0, b0[0], b0[1]);
            mma16816(acc[0][1], a0, b0[2], b0[3]);
            mma16816(acc[0][2], a0, b1[0], b1[1]);
            mma16816(acc[0][3], a0, b1[2], b1[3]);
            mma16816(acc[1][0], a1, b0[0], b0[1]);
            mma16816(acc[1][1], a1, b0[2], b0[3]);
            mma16816(acc[1][2], a1, b1[0], b1[1]);
            mma16816(acc[1][3], a1, b1[2], b1[3]);
        }
        if (kc == 0) __syncthreads();
    }

    int rr = lane >> 2, cc2 = 2*(lane & 3);
    #pragma unroll
    for (int mi = 0; mi < 2; mi++) {
        #pragma unroll
        for (int half = 0; half < 2; half++) {
            int f = fbase0 + wm*32 + mi*16 + rr + half*8;
            float bia = (f < 64) ? g_cbias[b*64 + f] : g_bias[f];
            bool isv = (f >= 64) && (f < 320);
            bool isy = (f < 64) || (f == 320);
            #pragma unroll
            for (int nj = 0; nj < 4; nj++) {
                float v0 = acc[mi][nj][half*2 + 0] + bia;
                float v1 = acc[mi][nj][half*2 + 1] + bia;
                int n = n0g + wn*32 + nj*8 + cc2;
                if (isv) {
                    v0 = fmaxf(v0, 0.f); v1 = fmaxf(v1, 0.f);
                    *(uint32_t*)(g_Vb + ((size_t)b*CH + (f - 64))*NPIX + n) = h2pk(v0, v1);
                } else if (isy) {
                    float* yp = g_Y + ((size_t)b*FTOT + f)*NPIX + n;
                    yp[0] = v0; yp[1] = v1;
                }
            }
        }
    }
}

// ---------------- pm softmax (row 320) ----------------
__global__ void __launch_bounds__(1024) masksoftmax_kernel() {
    int b = blockIdx.x, t = threadIdx.x;
    float* row = g_Y + ((size_t)b*FTOT + 320)*NPIX;
    __shared__ float red[32];
    float4 v = ((const float4*)row)[t];
    float e0 = __expf(v.x), e1 = __expf(v.y), e2 = __expf(v.z), e3 = __expf(v.w);
    float s = (e0 + e1) + (e2 + e3);
    #pragma unroll
    for (int o = 16; o > 0; o >>= 1) s += __shfl_xor_sync(0xffffffffu, s, o);
    if ((t & 31) == 0) red[t >> 5] = s;
    __syncthreads();
    if (t < 32) {
        float v2 = red[t];
        #pragma unroll
        for (int o = 16; o > 0; o >>= 1) v2 += __shfl_xor_sync(0xffffffffu, v2, o);
        if (t == 0) red[0] = v2;
    }
    __syncthreads();
    float inv = 1.f / red[0];
    float4 o; o.x = e0*inv; o.y = e1*inv; o.z = e2*inv; o.w = e3*inv;
    ((float4*)row)[t] = o;
}

// ---------------- vmask[b,c] = sum_n vfp16[b,c,n]*mask[b,n] ----------------
__global__ void __launch_bounds__(128) vmask_kernel() {
    int c = blockIdx.x, b = blockIdx.y, t = threadIdx.x;
    const uint4* vrow = (const uint4*)(g_Vb + ((size_t)b*CH + c)*NPIX);
    const float4* mrow = (const float4*)(g_Y + ((size_t)b*FTOT + 320)*NPIX);
    __shared__ float red[4];
    float s = 0.f;
    #pragma unroll
    for (int r = 0; r < 4; r++) {
        int idx = t + r*128;
        uint4 vv = vrow[idx];
        float4 m0 = mrow[idx*2], m1 = mrow[idx*2 + 1];
        float2 f0 = __half22float2(*(__half2*)&vv.x);
        float2 f1 = __half22float2(*(__half2*)&vv.y);
        float2 f2 = __half22float2(*(__half2*)&vv.z);
        float2 f3 = __half22float2(*(__half2*)&vv.w);
        s += f0.x*m0.x + f0.y*m0.y + f1.x*m0.z + f1.y*m0.w;
        s += f2.x*m1.x + f2.y*m1.y + f3.x*m1.z + f3.y*m1.w;
    }
    #pragma unroll
    for (int o = 16; o > 0; o >>= 1) s += __shfl_xor_sync(0xffffffffu, s, o);
    if ((t & 31) == 0) red[t >> 5] = s;
    __syncthreads();
    if (t == 0) g_vmask[b*CH + c] = (red[0] + red[1]) + (red[2] + red[3]);
}

// ---------------- q/k fp32 (centered via cbias) -> fp16 transposed [n][d] ----------------
__global__ void __launch_bounds__(256) qkconv_kernel() {
    __shared__ float sm[32][132];
    int n0 = blockIdx.x*128;
    int isk = blockIdx.y;
    int b = blockIdx.z;
    int t = threadIdx.x;
    const float* Yq = g_Y + ((size_t)b*FTOT + isk*32)*NPIX;
    #pragma unroll
    for (int r = 0; r < 4; r++) {
        int i = t + r*256;
        int d = i >> 5, c4 = i & 31;
        float4 v = *(const float4*)&Yq[(size_t)d*NPIX + n0 + c4*4];
        sm[d][c4*4+0]=v.x; sm[d][c4*4+1]=v.y; sm[d][c4*4+2]=v.z; sm[d][c4*4+3]=v.w;
    }
    __syncthreads();
    uint32_t* dst = (isk ? g_Kb : g_Qb) + ((size_t)b*NPIX + n0)*16;
    #pragma unroll
    for (int r = 0; r < 8; r++) {
        int i = t + r*256;
        int n = i >> 4, jp = i & 15;
        dst[n*16 + jp] = h2pk(sm[2*jp][n], sm[2*jp+1][n]);
    }
}

// ---------------- attention v2: 64q CTAs, warp = 16q x 128c, 64-key tiles, 2 CTAs/SM ----------------
#define SM2_VMK 0
#define SM2_QS  1024
#define SM2_KS0 5120
#define SM2_KS1 9216
#define SM2_VS0 13312
#define SM2_VS1 46080
#define SM2_TOTAL 78848

__global__ void __launch_bounds__(256, 2) attn_kernel(float* __restrict__ out) {
    extern __shared__ __align__(128) char smem[];
    uint32_t sb = smem_u32(smem);
    float* vmk = (float*)(smem + SM2_VMK);
    int t = threadIdx.x, w = t >> 5, lane = t & 31;
    int mq = w & 3, chf = w >> 2;             // warp = query group mq (16q), c-half chf (128c)
    int b = blockIdx.y, m0 = blockIdx.x * 64;

    vmk[t] = g_vmask[b*CH + t];

    int lq = lane >> 3, lr = lane & 7;
    uint32_t lrow   = (uint32_t)((lq >> 1)*8 + lr);
    uint32_t lcsel  = (uint32_t)((lq & 1)*16);
    uint32_t arow   = (uint32_t)(lane & 15);
    uint32_t acsel  = (uint32_t)((lane >> 4)*16);
    uint32_t kxor   = (uint32_t)(((lr >> 1) & 3) << 4);   // 64B-row swizzle
    uint32_t vxor   = (uint32_t)(lr << 4);                // 128B-row swizzle

    // ---- prologue: Q (64q x 32d) + tile 0 ----
    {
        int m = t >> 2, j = t & 3;
        CPA16(sb + SM2_QS + m*64 + (((uint32_t)j*16) ^ ((((uint32_t)m >> 1) & 3) << 4)),
              (const char*)(g_Qb + ((size_t)b*NPIX + m0 + m)*16 + j*4));
    }
    {
        int n = t >> 2, j = t & 3;
        CPA16(sb + SM2_KS0 + n*64 + (((uint32_t)j*16) ^ ((((uint32_t)n >> 1) & 3) << 4)),
              (const char*)(g_Kb + ((size_t)b*NPIX + 0 + n)*16 + j*4));
        #pragma unroll
        for (int r = 0; r < 8; r++) {
            int idx = t + r*256;
            int c = idx >> 3, jj = idx & 7;
            CPA16(sb + SM2_VS0 + c*128 + (((uint32_t)jj*16) ^ (((uint32_t)c & 7) << 4)),
                  (const char*)(g_Vb + ((size_t)b*CH + c)*NPIX + 0 + jj*8));
        }
    }
    CPA_COMMIT();

    float d2[16][4];
    #pragma unroll
    for (int i = 0; i < 16; i++)
        #pragma unroll
        for (int j = 0; j < 4; j++) d2[i][j] = 0.f;
    float dden[4] = {0.f, 0.f, 0.f, 0.f};
    uint32_t aq[2][4];

    #pragma unroll 1
    for (int i = 0; i < 64; i++) {
        if (i < 63) {
            int n0 = (i + 1) << 6;
            uint32_t ksd = sb + (((i + 1) & 1) ? SM2_KS1 : SM2_KS0);
            uint32_t vsd = sb + (((i + 1) & 1) ? SM2_VS1 : SM2_VS0);
            {
                int n = t >> 2, j = t & 3;
                CPA16(ksd + n*64 + (((uint32_t)j*16) ^ ((((uint32_t)n >> 1) & 3) << 4)),
                      (const char*)(g_Kb + ((size_t)b*NPIX + n0 + n)*16 + j*4));
            }
            #pragma unroll
            for (int r = 0; r < 8; r++) {
                int idx = t + r*256;
                int c = idx >> 3, jj = idx & 7;
                CPA16(vsd + c*128 + (((uint32_t)jj*16) ^ (((uint32_t)c & 7) << 4)),
                      (const char*)(g_Vb + ((size_t)b*CH + c)*NPIX + n0 + jj*8));
            }
        }
        CPA_COMMIT();
        CPA_WAIT1();
        __syncthreads();

        if (i == 0) {
            uint32_t qbase = sb + SM2_QS + (mq*16 + arow)*64;
            ldsm4(aq[0], qbase + ((0  + acsel) ^ kxor));
            ldsm4(aq[1], qbase + ((32 + acsel) ^ kxor));
        }

        uint32_t ksb = sb + ((i & 1) ? SM2_KS1 : SM2_KS0);
        uint32_t vsb = sb + ((i & 1) ? SM2_VS1 : SM2_VS0);

        #pragma unroll
        for (int kk = 0; kk < 4; kk++) {
            float s0[4] = {0.f,0.f,0.f,0.f};
            float s1[4] = {0.f,0.f,0.f,0.f};
            uint32_t kb[4];
            uint32_t kbase = ksb + (kk*16 + lrow)*64;
            ldsm4(kb, kbase + ((0 + lcsel) ^ kxor));
            mma16816(s0, aq[0], kb[0], kb[1]);
            mma16816(s1, aq[0], kb[2], kb[3]);
            ldsm4(kb, kbase + ((32 + lcsel) ^ kxor));
            mma16816(s0, aq[1], kb[0], kb[1]);
            mma16816(s1, aq[1], kb[2], kb[3]);

            uint32_t pk[4];
            pk[0] = hexp2pk(s0[0], s0[1]);
            pk[1] = hexp2pk(s0[2], s0[3]);
            pk[2] = hexp2pk(s1[0], s1[1]);
            pk[3] = hexp2pk(s1[2], s1[3]);

            mma16816(dden, pk, ONESH, ONESH);

            uint32_t coloff = (uint32_t)(kk*32 + lcsel);
            #pragma unroll
            for (int c16 = 0; c16 < 8; c16++) {
                uint32_t vb[4];
                ldsm4(vb, vsb + ((uint32_t)(chf*128 + c16*16) + lrow)*128 + (coloff ^ vxor));
                mma16816(d2[c16*2],     pk, vb[0], vb[1]);
                mma16816(d2[c16*2 + 1], pk, vb[2], vb[3]);
            }
        }
        __syncthreads();
    }

    float i0 = 1.f / dden[0];
    float i1 = 1.f / dden[2];

    int mlo = m0 + mq*16 + (lane >> 2);
    int cb  = 2*(lane & 3);
    float* outb = out + OUTOFF + (size_t)b*CH*NPIX;
    #pragma unroll
    for (int cc = 0; cc < 16; cc++) {
        int c0 = chf*128 + cc*8 + cb;
        outb[(size_t)c0*NPIX + mlo]           = d2[cc][0]*i0 + vmk[c0];
        outb[(size_t)(c0+1)*NPIX + mlo]       = d2[cc][1]*i0 + vmk[c0+1];
        outb[(size_t)c0*NPIX + mlo + 8]       = d2[cc][2]*i1 + vmk[c0];
        outb[(size_t)(c0+1)*NPIX + mlo + 8]   = d2[cc][3]*i1 + vmk[c0+1];
    }
}

// ---------------- launch ----------------
extern "C" void kernel_launch(void* const* d_in, const int* in_sizes, int n_in,
                              void* d_out, int out_size) {
    const float* x  = (const float*)d_in[0];
    const float* wq = (const float*)d_in[1];
    const float* bq = (const float*)d_in[2];
    const float* wk = (const float*)d_in[3];
    const float* bk = (const float*)d_in[4];
    const float* wv = (const float*)d_in[5];
    const float* bv = (const float*)d_in[6];
    const float* wm = (const float*)d_in[7];
    const float* bm = (const float*)d_in[8];
    float* out = (float*)d_out;
    (void)bq; (void)bk;   // q/k biases cancel under spatial centering

    cudaFuncSetAttribute(attn_kernel,  cudaFuncAttributeMaxDynamicSharedMemorySize, SM2_TOTAL);
    cudaFuncSetAttribute(gemm2_kernel, cudaFuncAttributeMaxDynamicSharedMemorySize, GEMM_SMEM);

    pack_kernel<<<128, 256>>>(wq, bq, wk, bk, wv, bv, wm, bm);
    xconv_kernel<<<dim3(NPIX/128, CH/64, BATCH), 256>>>(x, out);
    cbias_kernel<<<BATCH, 64>>>();
    gemm2_kernel<<<dim3(NPIX/64, 3, BATCH), 256, GEMM_SMEM>>>();
    masksoftmax_kernel<<<BATCH, 1024>>>();
    vmask_kernel<<<dim3(CH, BATCH), 128>>>();
    qkconv_kernel<<<dim3(NPIX/128, 2, BATCH), 256>>>();
    attn_kernel<<<dim3(NPIX/64, BATCH), 256, SM2_TOTAL>>>(out);
}